// round 13
// baseline (speedup 1.0000x reference)
#include <cuda_runtime.h>
#include <cuda_bf16.h>

// ---------------------------------------------------------------------------
// HardTripletMiningLoss  (n=3B=480, D=128)
//   gram = E E^T ;  pd[i,j] = max(sq_i + sq_j - 2 gram_ij, 0)
//   loss = mean over {i!=0, lab[i]==lab[j], lab[k]!=lab[j], td>0} of
//          td = pd[i,j] - pd[j,k] + A
// R13: gram = 128-thr blocks, 32x32 tile, 2x4/thread, KSPLIT=4 (Kc=32):
//      900 blocks (occupancy) AND 256 FMA/thread vs ~140 overhead instrs
//      (amortization). PDL chain gram -> triplet -> final kept from R12.
// ---------------------------------------------------------------------------

#define MAX_N    768
#define MAXW     ((MAX_N + 31) / 32)
#define POSCAP   128
#define MARGIN_A 0.2f
#define TILE     32      // gram tile rows == cols
#define KSPLIT   4
#define KC       32      // D / KSPLIT for D=128
#define ASTR     36      // As row stride (mult of 4, banks 8/16/24/0 for rows)

static __device__ float g_part[KSPLIT][MAX_N * MAX_N];
static __device__ float g_sqp [KSPLIT][MAX_N];
static __device__ float g_ps[MAX_N];
static __device__ int   g_pc[MAX_N];

__device__ __forceinline__ void pdl_wait() {
    asm volatile("griddepcontrol.wait;" ::: "memory");
}
__device__ __forceinline__ void pdl_launch_dependents() {
    asm volatile("griddepcontrol.launch_dependents;" ::: "memory");
}

__device__ __forceinline__ const float* row_ptr(const float* a, const float* p,
                                                const float* ng, int r, int B, int D) {
    if (r < B)      return a  + (size_t)r * D;
    if (r < 2 * B)  return p  + (size_t)(r - B) * D;
    return ng + (size_t)(r - 2 * B) * D;
}

// ---------------------------------------------------------------------------
// gram: grid (15, 15, KSPLIT), 128 thr, 32x32 tile, 2 rows x 4 cols / thread.
// Inner loop per k: 2 scalar LDS (4-way distinct, conflict-free) +
// 1 LDS.128 (128 B distinct, broadcast across lane groups) + 8 FMA.
// ---------------------------------------------------------------------------
__global__ void gram_kernel(const float* __restrict__ anchor,
                            const float* __restrict__ positive,
                            const float* __restrict__ negative,
                            int n, int B, int D) {
    __shared__ float As[TILE][ASTR];    // row-major over k
    __shared__ float BsT[KC][TILE];     // k-major transposed

    const int bi  = blockIdx.y * TILE;
    const int bj  = blockIdx.x * TILE;
    const int z   = blockIdx.z;
    const int k0  = z * KC;
    const int tid = threadIdx.x;        // 128 threads

    // load As: 32 rows x 8 float4 = 256 loads -> 2 per thread
    #pragma unroll
    for (int l = 0; l < 2; l++) {
        const int idx = tid + l * 128;
        const int r   = idx >> 3;       // 0..31
        const int c4  = idx & 7;        // 0..7
        const int gr  = (bi + r < n) ? bi + r : n - 1;
        const float4 v = *(const float4*)(row_ptr(anchor, positive, negative, gr, B, D) + k0 + c4 * 4);
        *(float4*)&As[r][c4 * 4] = v;
    }
    // load BsT transposed: 32 cols x 8 float4 = 256 loads -> 2 per thread
    #pragma unroll
    for (int l = 0; l < 2; l++) {
        const int idx = tid + l * 128;
        const int col = idx & 31;
        const int c4  = idx >> 5;       // 0..7
        const int gc  = (bj + col < n) ? bj + col : n - 1;
        const float4 v = *(const float4*)(row_ptr(anchor, positive, negative, gc, B, D) + k0 + c4 * 4);
        const int k = c4 * 4;
        BsT[k + 0][col] = v.x;          // row stride 32 words: bank == col
        BsT[k + 1][col] = v.y;
        BsT[k + 2][col] = v.z;
        BsT[k + 3][col] = v.w;
    }
    __syncthreads();

    const int tx = tid & 7;             // 8 col-groups x 4 cols = 32
    const int ty = tid >> 3;            // 16 row-groups x 2 rows = 32
    const int r0 = ty * 2;
    const int c0 = tx * 4;

    float a0x = 0.f, a0y = 0.f, a0z = 0.f, a0w = 0.f;
    float a1x = 0.f, a1y = 0.f, a1z = 0.f, a1w = 0.f;

    #pragma unroll
    for (int k = 0; k < KC; k++) {
        const float x0 = As[r0][k];
        const float x1 = As[r0 + 1][k];
        const float4 b = *(const float4*)&BsT[k][c0];
        a0x = fmaf(x0, b.x, a0x);
        a0y = fmaf(x0, b.y, a0y);
        a0z = fmaf(x0, b.z, a0z);
        a0w = fmaf(x0, b.w, a0w);
        a1x = fmaf(x1, b.x, a1x);
        a1y = fmaf(x1, b.y, a1y);
        a1z = fmaf(x1, b.z, a1z);
        a1w = fmaf(x1, b.w, a1w);
    }

    float* gp = g_part[z];
    const int gi0 = bi + r0;
    const int gj0 = bj + c0;
    if (gj0 < n) {                       // n%4==0 -> float4 in-bounds
        if (gi0 < n) {
            float4 v; v.x = a0x; v.y = a0y; v.z = a0z; v.w = a0w;
            *(float4*)&gp[(size_t)gi0 * n + gj0] = v;
            const int dq = gi0 - gj0;
            if (dq >= 0 && dq < 4) g_sqp[z][gi0] = (&v.x)[dq];
        }
        if (gi0 + 1 < n) {
            float4 v; v.x = a1x; v.y = a1y; v.z = a1z; v.w = a1w;
            *(float4*)&gp[(size_t)(gi0 + 1) * n + gj0] = v;
            const int dq = gi0 + 1 - gj0;
            if (dq >= 0 && dq < 4) g_sqp[z][gi0 + 1] = (&v.x)[dq];
        }
    }
    pdl_launch_dependents();
}

// ---------------------------------------------------------------------------
// Triplet: one block (128 thr) per j. Label work BEFORE pdl_wait (overlaps
// gram); gram-dependent work after. Branch-free fp32 hot loop.
// ---------------------------------------------------------------------------
__global__ void triplet_kernel(const int* __restrict__ ind, int n) {
    __shared__ float    pdrow[MAX_N];
    __shared__ int      labs[MAX_N];
    __shared__ short    slist[POSCAP];
    __shared__ float    avals[POSCAP];
    __shared__ unsigned chunkMask[MAXW];
    __shared__ int      chunkOff[MAXW];
    __shared__ int      nSame;
    __shared__ float    red_s[4];
    __shared__ int      red_c[4];

    const int j    = blockIdx.x;
    const int tid  = threadIdx.x;
    const int lane = tid & 31;
    const int wid  = tid >> 5;

    // ---------------- pre-wait: everything independent of gram --------------
    for (int t = tid; t < n; t += 128)
        labs[t] = ind[t];
    __syncthreads();

    const int labj = labs[j];

    const int nChunks = (n + 31) >> 5;
    for (int c = wid; c < nChunks; c += 4) {
        const int t = (c << 5) + lane;
        const bool pred = (t < n) && (t != 0) && (labs[t] == labj);
        const unsigned m = __ballot_sync(0xffffffffu, pred);
        if (lane == 0) chunkMask[c] = m;
    }
    __syncthreads();
    if (wid == 0) {                       // warp scan (nChunks <= 32)
        const unsigned m = (lane < nChunks) ? chunkMask[lane] : 0u;
        int p = __popc(m);
        #pragma unroll
        for (int o = 1; o < 32; o <<= 1) {
            const int t = __shfl_up_sync(0xffffffffu, p, o);
            if (lane >= o) p += t;
        }
        if (lane < nChunks) chunkOff[lane] = p - __popc(m);
        if (lane == 31) nSame = p;
    }
    __syncthreads();
    for (int c = wid; c < nChunks; c += 4) {
        const unsigned m = chunkMask[c];
        const int t = (c << 5) + lane;
        if ((m >> lane) & 1u) {
            const int off = chunkOff[c] + __popc(m & ((1u << lane) - 1u));
            if (off < POSCAP) slist[off] = (short)t;
        }
    }
    __syncthreads();

    // ---------------- wait for gram, then consume its output ----------------
    pdl_wait();

    float sqj = g_sqp[0][j];
    #pragma unroll
    for (int z = 1; z < KSPLIT; z++) sqj += g_sqp[z][j];

    const size_t roff = (size_t)j * n;
    const int n4 = n >> 2;
    for (int v = tid; v < n4; v += 128) {
        float4 g = ((const float4*)(g_part[0] + roff))[v];
        float4 q = ((const float4*)g_sqp[0])[v];
        #pragma unroll
        for (int z = 1; z < KSPLIT; z++) {
            const float4 gz = ((const float4*)(g_part[z] + roff))[v];
            const float4 qz = ((const float4*)g_sqp[z])[v];
            g.x += gz.x; g.y += gz.y; g.z += gz.z; g.w += gz.w;
            q.x += qz.x; q.y += qz.y; q.z += qz.z; q.w += qz.w;
        }
        float4 pd;
        pd.x = fmaxf(fmaf(-2.f, g.x, sqj + q.x), 0.f);
        pd.y = fmaxf(fmaf(-2.f, g.y, sqj + q.y), 0.f);
        pd.z = fmaxf(fmaf(-2.f, g.z, sqj + q.z), 0.f);
        pd.w = fmaxf(fmaf(-2.f, g.w, sqj + q.w), 0.f);
        ((float4*)pdrow)[v] = pd;
    }
    for (int v = (n4 << 2) + tid; v < n; v += 128) {
        float g = 0.f, q = 0.f;
        #pragma unroll
        for (int z = 0; z < KSPLIT; z++) { g += g_part[z][roff + v]; q += g_sqp[z][v]; }
        pdrow[v] = fmaxf(fmaf(-2.f, g, sqj + q), 0.f);
    }
    __syncthreads();

    const int ns = (nSame < POSCAP) ? nSame : POSCAP;
    if (tid < ns)
        avals[tid] = pdrow[(int)slist[tid]] + MARGIN_A;

    float pdk[4];
    #pragma unroll
    for (int m = 0; m < 4; m++) pdk[m] = 3.4e38f;   // sentinel: never counted
    {
        int m = 0;
        for (int k = tid; k < n; k += 128, m++)
            if (labs[k] != labj) pdk[m] = pdrow[k];
    }
    __syncthreads();

    float s = 0.f;
    int   c = 0;
    for (int q = 0; q < ns; q++) {
        const float aq = avals[q];
        #pragma unroll
        for (int m = 0; m < 4; m++) {
            const float v = aq - pdk[m];
            if (v > 0.f) { s += v; c++; }
        }
    }

    #pragma unroll
    for (int o = 16; o > 0; o >>= 1) {
        s += __shfl_down_sync(0xffffffffu, s, o);
        c += __shfl_down_sync(0xffffffffu, c, o);
    }
    if (lane == 0) { red_s[wid] = s; red_c[wid] = c; }
    __syncthreads();
    if (tid == 0) {
        float st = 0.f; int ct = 0;
        #pragma unroll
        for (int w = 0; w < 4; w++) { st += red_s[w]; ct += red_c[w]; }
        g_ps[j] = st;
        g_pc[j] = ct;
    }
    pdl_launch_dependents();
}

// ---------------------------------------------------------------------------
// Final: single block, fp64 reduce of n partials (waits on triplet via PDL).
// ---------------------------------------------------------------------------
__global__ void final_kernel(float* __restrict__ out, int n) {
    __shared__ double red_s[4];
    __shared__ double red_c[4];
    const int tid  = threadIdx.x;
    const int lane = tid & 31;
    const int wid  = tid >> 5;

    pdl_wait();

    double s = 0.0, c = 0.0;
    for (int t = tid; t < n; t += 128) { s += (double)g_ps[t]; c += (double)g_pc[t]; }
    #pragma unroll
    for (int o = 16; o > 0; o >>= 1) {
        s += __shfl_down_sync(0xffffffffu, s, o);
        c += __shfl_down_sync(0xffffffffu, c, o);
    }
    if (lane == 0) { red_s[wid] = s; red_c[wid] = c; }
    __syncthreads();
    if (tid == 0) {
        double st = 0.0, ct = 0.0;
        #pragma unroll
        for (int w = 0; w < 4; w++) { st += red_s[w]; ct += red_c[w]; }
        out[0] = (ct > 0.0) ? (float)(st / (ct < 1.0 ? 1.0 : ct)) : 0.0f;
    }
}

extern "C" void kernel_launch(void* const* d_in, const int* in_sizes, int n_in,
                              void* d_out, int out_size) {
    const float* anchor   = (const float*)d_in[0];
    const float* positive = (const float*)d_in[1];
    const float* negative = (const float*)d_in[2];
    const int*   ind      = (const int*)d_in[3];

    const int n = in_sizes[3];          // 3B
    const int B = n / 3;
    const int D = in_sizes[0] / B;      // 128

    dim3 ggrid((n + TILE - 1) / TILE, (n + TILE - 1) / TILE, KSPLIT); // 15x15x4
    gram_kernel<<<ggrid, 128>>>(anchor, positive, negative, n, B, D);

    cudaLaunchAttribute attr[1];
    attr[0].id = cudaLaunchAttributeProgrammaticStreamSerialization;
    attr[0].val.programmaticStreamSerializationAllowed = 1;

    cudaLaunchConfig_t cfg = {};
    cfg.attrs = attr;
    cfg.numAttrs = 1;
    cfg.stream = 0;

    cfg.gridDim  = dim3((unsigned)n, 1, 1);
    cfg.blockDim = dim3(128, 1, 1);
    cudaLaunchKernelEx(&cfg, triplet_kernel, ind, n);

    cfg.gridDim  = dim3(1, 1, 1);
    cfg.blockDim = dim3(128, 1, 1);
    cudaLaunchKernelEx(&cfg, final_kernel, (float*)d_out, n);
}